// round 14
// baseline (speedup 1.0000x reference)
#include <cuda_runtime.h>
#include <cuda_bf16.h>
#include <cstdint>

#define TT 2048
#define CC 64
#define NCH 32
#define NT 512

// K tiles [64s x 128m] stride 272, double-buffered. MT [64n x 128m] 272.
// VT [64n x 64s] 144. A [64t x 64s] 144. Scalars parity double-buffered.
#define S_K0H 0
#define S_K0L 17408
#define S_K1H 34816
#define S_K1L 52224
#define S_MH  69632
#define S_ML  87040
#define S_VH  104448
#define S_VL  113664
#define S_AH  122880
#define S_AL  132096
#define S_G   141312
#define S_WS  141824
#define S_WG  142336
#define S_EG  142848
#define S_SC  143360
#define SMEMB 143392

static __device__ __forceinline__ uint32_t su32(const void* p) {
    uint32_t a;
    asm("{ .reg .u64 t; cvta.to.shared.u64 t, %1; cvt.u32.u64 %0, t; }" : "=r"(a) : "l"(p));
    return a;
}
static __device__ __forceinline__ void ldmA(uint32_t a[4], uint32_t addr) {
    asm volatile("ldmatrix.sync.aligned.m8n8.x4.shared.b16 {%0,%1,%2,%3}, [%4];"
        : "=r"(a[0]), "=r"(a[1]), "=r"(a[2]), "=r"(a[3]) : "r"(addr));
}
static __device__ __forceinline__ void ldmB4(uint32_t b[4], uint32_t addr) {
    asm volatile("ldmatrix.sync.aligned.m8n8.x4.shared.b16 {%0,%1,%2,%3}, [%4];"
        : "=r"(b[0]), "=r"(b[1]), "=r"(b[2]), "=r"(b[3]) : "r"(addr));
}
static __device__ __forceinline__ void ldmT(uint32_t a[4], uint32_t addr) {
    asm volatile("ldmatrix.sync.aligned.m8n8.x4.trans.shared.b16 {%0,%1,%2,%3}, [%4];"
        : "=r"(a[0]), "=r"(a[1]), "=r"(a[2]), "=r"(a[3]) : "r"(addr));
}
static __device__ __forceinline__ void mma16(float c[4], const uint32_t a[4], uint32_t b0, uint32_t b1) {
    asm volatile("mma.sync.aligned.m16n8k16.row.col.f32.bf16.bf16.f32 "
        "{%0,%1,%2,%3}, {%4,%5,%6,%7}, {%8,%9}, {%0,%1,%2,%3};"
        : "+f"(c[0]), "+f"(c[1]), "+f"(c[2]), "+f"(c[3])
        : "r"(a[0]), "r"(a[1]), "r"(a[2]), "r"(a[3]), "r"(b0), "r"(b1));
}
static __device__ __forceinline__ void spl(float x, __nv_bfloat16& h, __nv_bfloat16& l) {
    h = __float2bfloat16_rn(x);
    l = __float2bfloat16_rn(x - __bfloat162float(h));
}
static __device__ __forceinline__ void sp2(float x0, float x1, uint32_t& hi, uint32_t& lo) {
    __nv_bfloat16 h0, l0, h1, l1;
    spl(x0, h0, l0); spl(x1, h1, l1);
    hi = (uint32_t)__bfloat16_as_ushort(h0) | ((uint32_t)__bfloat16_as_ushort(h1) << 16);
    lo = (uint32_t)__bfloat16_as_ushort(l0) | ((uint32_t)__bfloat16_as_ushort(l1) << 16);
}
// exp2(x) for x <= 0, FFMA-only
static __device__ __forceinline__ float ex2n(float x) {
    float xc = fmaxf(x, -150.f);
    float xf = floorf(xc);
    float f  = xc - xf;
    float p = 1.54035e-4f;
    p = fmaf(p, f, 1.3335581e-3f);
    p = fmaf(p, f, 9.6181291e-3f);
    p = fmaf(p, f, 5.5504109e-2f);
    p = fmaf(p, f, 2.4022651e-1f);
    p = fmaf(p, f, 6.9314718e-1f);
    p = fmaf(p, f, 1.0f);
    float r = __int_as_float(__float_as_int(p) + (((int)xf) << 23));
    return (xc <= -126.f) ? 0.f : r;
}

__global__ void __launch_bounds__(NT, 1)
lmm_hmma(const float* __restrict__ q, const float* __restrict__ kk,
         const float* __restrict__ v, const float* __restrict__ alpha,
         const float* __restrict__ rho, const float* __restrict__ lam,
         const float* __restrict__ init, float* __restrict__ out)
{
    extern __shared__ char sm[];
    const uint32_t sb = su32(sm);
    const int tid = threadIdx.x, warp = tid >> 5, lane = tid & 31;
    const int gid = lane >> 2, tig = lane & 3;
    const int b = blockIdx.x >> 1, vh = blockIdx.x & 1;
    const int rt = warp >> 2, ct = warp & 3;   // S / QM0 / AV: 16x16 tile (rt, ct)
    const int wr = warp >> 1, wc = warp & 1;   // dM / M0: rows wr*16.., cols wc*32..
    const bool sact = (ct <= rt);

    const uint32_t laneA144 = (uint32_t)(lane & 15) * 144u + (uint32_t)((lane >> 4) << 4);
    const uint32_t laneB272x4 = (uint32_t)(lane & 7) * 272u + (uint32_t)(((lane >> 3) & 1) << 4)
                              + (uint32_t)(lane >> 4) * (8u * 272u);
    const uint32_t laneB144x4 = (uint32_t)(lane & 7) * 144u + (uint32_t)(((lane >> 3) & 1) << 4)
                              + (uint32_t)(lane >> 4) * (8u * 144u);
    const uint32_t laneT = ((uint32_t)(lane & 7) + (uint32_t)((lane >> 4) << 3)) * 272u
                         + (uint32_t)(lane & 8) * 2u;

    // scalar computation for chunk at tbX into parity buffers
    auto do_scalars = [&](size_t tbX, int parX) {
        float* Gp  = (float*)(sm + S_G)  + parX * 64;
        float* WSp = (float*)(sm + S_WS) + parX * 64;
        float* WGp = (float*)(sm + S_WG) + parX * 64;
        float* EGp = (float*)(sm + S_EG) + parX * 64;
        float x = log2f(fmaxf(lam[tbX + lane], 1e-37f));
        #pragma unroll
        for (int o = 1; o < 32; o <<= 1) { float y = __shfl_up_sync(~0u, x, o); if (lane >= o) x += y; }
        float tot = __shfl_sync(~0u, x, 31);
        float y2 = log2f(fmaxf(lam[tbX + 32 + lane], 1e-37f));
        #pragma unroll
        for (int o = 1; o < 32; o <<= 1) { float y = __shfl_up_sync(~0u, y2, o); if (lane >= o) y2 += y; }
        float g2 = tot + y2;
        float g63 = __shfl_sync(~0u, g2, 31);
        float w0 = rho[tbX + lane] * alpha[tbX + lane];
        float w1 = rho[tbX + 32 + lane] * alpha[tbX + 32 + lane];
        Gp[lane] = x;            Gp[32 + lane] = g2;
        WSp[lane] = w0;          WSp[32 + lane] = w1;
        EGp[lane] = ex2n(x);     EGp[32 + lane] = ex2n(g2);
        WGp[lane] = ex2n(g63 - x) * w0;
        WGp[32 + lane] = ex2n(g63 - g2) * w1;
        if (lane == 31) ((float*)(sm + S_SC))[parX] = ex2n(g63);
    };

    // ---- M0 in registers: warp owns rows [wr*16,+16), cols [wc*32,+32) ----
    const int mr0 = wr * 16 + gid, mr1 = mr0 + 8;
    float m0[4][4];
    {
        const float* ip = init + (size_t)b * 16384 + vh * 64;
        #pragma unroll
        for (int j = 0; j < 4; j++) {
            int n = wc * 32 + 8 * j + 2 * tig;
            float2 f0 = *(const float2*)(ip + (size_t)mr0 * 128 + n);
            float2 f1 = *(const float2*)(ip + (size_t)mr1 * 128 + n);
            m0[j][0] = f0.x; m0[j][1] = f0.y; m0[j][2] = f1.x; m0[j][3] = f1.y;
        }
    }
    #pragma unroll
    for (int j = 0; j < 4; j++) {
        int n = wc * 32 + 8 * j + 2 * tig;
        #pragma unroll
        for (int e = 0; e < 4; e++) {
            int nn = n + (e & 1), m = (e < 2) ? mr0 : mr1;
            __nv_bfloat16 h, l; spl(m0[j][e], h, l);
            uint32_t o = (uint32_t)nn * 272u + ((uint32_t)m << 1);
            *(__nv_bfloat16*)(sm + S_MH + o) = h;
            *(__nv_bfloat16*)(sm + S_ML + o) = l;
        }
    }
    // K(0) tiles -> buf0
    {
        const size_t t0 = (size_t)b * TT;
        for (int i = tid; i < 2048; i += NT) {
            int t = i >> 5, c4 = (i & 31) << 2;
            uint32_t o = (uint32_t)t * 272u + (uint32_t)(c4 << 1);
            float4 f = *(const float4*)(kk + (t0 + t) * 128 + c4);
            uint32_t h0, l0, h1, l1;
            sp2(f.x, f.y, h0, l0); sp2(f.z, f.w, h1, l1);
            *(uint32_t*)(sm + S_K0H + o) = h0; *(uint32_t*)(sm + S_K0H + o + 4) = h1;
            *(uint32_t*)(sm + S_K0L + o) = l0; *(uint32_t*)(sm + S_K0L + o + 4) = l1;
        }
    }
    if (warp == 0) do_scalars((size_t)b * TT, 0);
    // V(0) + K(1) prefetch
    float vreg[8];
    #pragma unroll
    for (int ii = 0; ii < 8; ii++) {
        int i = tid + ii * NT;
        vreg[ii] = v[((size_t)b * TT + (size_t)(i >> 6)) * 128 + vh * 64 + (i & 63)];
    }
    float4 kreg[4];
    #pragma unroll
    for (int ii = 0; ii < 4; ii++) {
        int i = tid + ii * NT;
        kreg[ii] = *(const float4*)(kk + ((size_t)b * TT + CC + (size_t)(i >> 5)) * 128 + ((i & 31) << 2));
    }
    __syncthreads();

    // ---- prologue S(0) GEMM ----
    float sS[2][4];
    #pragma unroll
    for (int j = 0; j < 2; j++)
        #pragma unroll
        for (int e = 0; e < 4; e++) sS[j][e] = 0.f;
    if (sact) {
        const float* qr0 = q + ((size_t)b * TT + (size_t)(rt * 16 + gid)) * 128 + 2 * tig;
        const uint32_t col = (uint32_t)(ct * 16);
        #pragma unroll
        for (int ks = 0; ks < 8; ks++) {
            uint32_t qa[4], ql[4];
            float2 f0 = *(const float2*)(qr0 + ks * 16);
            float2 f1 = *(const float2*)(qr0 + 8 * 128 + ks * 16);
            float2 f2 = *(const float2*)(qr0 + ks * 16 + 8);
            float2 f3 = *(const float2*)(qr0 + 8 * 128 + ks * 16 + 8);
            sp2(f0.x, f0.y, qa[0], ql[0]); sp2(f1.x, f1.y, qa[1], ql[1]);
            sp2(f2.x, f2.y, qa[2], ql[2]); sp2(f3.x, f3.y, qa[3], ql[3]);
            uint32_t bh[4], bl[4];
            uint32_t kB = sb + S_K0H + col * 272u + ks * 32 + laneB272x4;
            ldmB4(bh, kB); ldmB4(bl, kB + 17408u);
            mma16(sS[0], qa, bh[0], bh[1]); mma16(sS[0], qa, bl[0], bl[1]); mma16(sS[0], ql, bh[0], bh[1]);
            mma16(sS[1], qa, bh[2], bh[3]); mma16(sS[1], qa, bl[2], bl[3]); mma16(sS[1], ql, bh[2], bh[3]);
        }
    }

    for (int c = 0; c < NCH; c++) {
        const size_t tb0 = (size_t)b * TT + (size_t)c * CC;
        const int par = c & 1;
        const uint32_t kbH = par ? S_K1H : S_K0H;
        const uint32_t nbH = par ? S_K0H : S_K1H;
        float* Gs  = (float*)(sm + S_G)  + par * 64;
        float* WSs = (float*)(sm + S_WS) + par * 64;
        float* WGs = (float*)(sm + S_WG) + par * 64;
        float* EGs = (float*)(sm + S_EG) + par * 64;

        // ======== PHASE 1: A-build(c), V^T(c) store, K(c+1) STS, QM0 GEMM ========
        if (sact) {
            int t0 = rt * 16 + gid, t1 = t0 + 8;
            float g0 = Gs[t0], g1 = Gs[t1];
            #pragma unroll
            for (int j = 0; j < 2; j++) {
                int s0 = ct * 16 + 8 * j + 2 * tig, s1 = s0 + 1;
                float gs0 = Gs[s0], gs1 = Gs[s1], w0 = WSs[s0], w1 = WSs[s1];
                float a00 = (t0 >= s0) ? ex2n(g0 - gs0) * w0 * sS[j][0] : 0.f;
                float a01 = (t0 >= s1) ? ex2n(g0 - gs1) * w1 * sS[j][1] : 0.f;
                float a10 = (t1 >= s0) ? ex2n(g1 - gs0) * w0 * sS[j][2] : 0.f;
                float a11 = (t1 >= s1) ? ex2n(g1 - gs1) * w1 * sS[j][3] : 0.f;
                uint32_t hi, lo;
                sp2(a00, a01, hi, lo);
                uint32_t o = (uint32_t)t0 * 144u + (uint32_t)(s0 << 1);
                *(uint32_t*)(sm + S_AH + o) = hi; *(uint32_t*)(sm + S_AL + o) = lo;
                sp2(a10, a11, hi, lo);
                o = (uint32_t)t1 * 144u + (uint32_t)(s0 << 1);
                *(uint32_t*)(sm + S_AH + o) = hi; *(uint32_t*)(sm + S_AL + o) = lo;
            }
        }
        // V^T(c) store
        #pragma unroll
        for (int ii = 0; ii < 8; ii++) {
            int i = tid + ii * NT;
            int s = i >> 6, n = i & 63;
            __nv_bfloat16 h, l; spl(vreg[ii], h, l);
            uint32_t o = (uint32_t)n * 144u + (uint32_t)(s << 1);
            *(__nv_bfloat16*)(sm + S_VH + o) = h;
            *(__nv_bfloat16*)(sm + S_VL + o) = l;
        }
        // K(c+1) STS
        #pragma unroll
        for (int ii = 0; ii < 4; ii++) {
            int i = tid + ii * NT;
            int t = i >> 5, c4 = (i & 31) << 2;
            uint32_t o = (uint32_t)t * 272u + (uint32_t)(c4 << 1);
            uint32_t h0, l0, h1, l1;
            sp2(kreg[ii].x, kreg[ii].y, h0, l0); sp2(kreg[ii].z, kreg[ii].w, h1, l1);
            *(uint32_t*)(sm + nbH + o) = h0; *(uint32_t*)(sm + nbH + o + 4) = h1;
            *(uint32_t*)(sm + nbH + 17408u + o) = l0; *(uint32_t*)(sm + nbH + 17408u + o + 4) = l1;
        }
        // QM0 GEMM: q(c) frags x M^T(c)
        float sQ[2][4];
        #pragma unroll
        for (int j = 0; j < 2; j++)
            #pragma unroll
            for (int e = 0; e < 4; e++) sQ[j][e] = 0.f;
        {
            const float* qr0 = q + (tb0 + (size_t)(rt * 16 + gid)) * 128 + 2 * tig;
            const uint32_t col = (uint32_t)(ct * 16);
            #pragma unroll
            for (int ks = 0; ks < 8; ks++) {
                uint32_t qa[4], ql[4];
                float2 f0 = *(const float2*)(qr0 + ks * 16);
                float2 f1 = *(const float2*)(qr0 + 8 * 128 + ks * 16);
                float2 f2 = *(const float2*)(qr0 + ks * 16 + 8);
                float2 f3 = *(const float2*)(qr0 + 8 * 128 + ks * 16 + 8);
                sp2(f0.x, f0.y, qa[0], ql[0]); sp2(f1.x, f1.y, qa[1], ql[1]);
                sp2(f2.x, f2.y, qa[2], ql[2]); sp2(f3.x, f3.y, qa[3], ql[3]);
                uint32_t bh[4], bl[4];
                uint32_t mB = sb + S_MH + col * 272u + ks * 32 + laneB272x4;
                ldmB4(bh, mB); ldmB4(bl, mB + (S_ML - S_MH));
                mma16(sQ[0], qa, bh[0], bh[1]); mma16(sQ[0], qa, bl[0], bl[1]); mma16(sQ[0], ql, bh[0], bh[1]);
                mma16(sQ[1], qa, bh[2], bh[3]); mma16(sQ[1], qa, bl[2], bl[3]); mma16(sQ[1], ql, bh[2], bh[3]);
            }
        }
        __syncthreads();   // sync A: A(c), V^T(c), K(c+1) visible

        // ======== PHASE 2: scalars(c+1), AV, dM, S(c+1), readout, M^T(c+1) ========
        if (warp == 0 && c + 1 < NCH) do_scalars(tb0 + CC, par ^ 1);
        // prefetch V(c+1), K(c+2)
        {
            const size_t tbv = tb0 + ((c + 1 < NCH) ? CC : 0);
            #pragma unroll
            for (int ii = 0; ii < 8; ii++) {
                int i = tid + ii * NT;
                vreg[ii] = v[(tbv + (size_t)(i >> 6)) * 128 + vh * 64 + (i & 63)];
            }
            const size_t tbk = tb0 + ((c + 2 < NCH) ? 2 * CC : 0);
            #pragma unroll
            for (int ii = 0; ii < 4; ii++) {
                int i = tid + ii * NT;
                kreg[ii] = *(const float4*)(kk + (tbk + (size_t)(i >> 5)) * 128 + ((i & 31) << 2));
            }
        }
        // AV GEMM (ks <= rt)
        float sA[2][4];
        #pragma unroll
        for (int j = 0; j < 2; j++)
            #pragma unroll
            for (int e = 0; e < 4; e++) sA[j][e] = 0.f;
        {
            const uint32_t ahB = sb + S_AH + (uint32_t)(rt * 16) * 144u + laneA144;
            #pragma unroll
            for (int ks = 0; ks < 4; ks++) {
                if (ks <= rt) {
                    uint32_t aa[4], al[4];
                    ldmA(aa, ahB + ks * 32); ldmA(al, ahB + (S_AL - S_AH) + ks * 32);
                    uint32_t bh[4], bl[4];
                    uint32_t vB = sb + S_VH + (uint32_t)(ct * 16) * 144u + ks * 32 + laneB144x4;
                    ldmB4(bh, vB); ldmB4(bl, vB + (S_VL - S_VH));
                    mma16(sA[0], aa, bh[0], bh[1]); mma16(sA[0], aa, bl[0], bl[1]); mma16(sA[0], al, bh[0], bh[1]);
                    mma16(sA[1], aa, bh[2], bh[3]); mma16(sA[1], aa, bl[2], bl[3]); mma16(sA[1], al, bh[2], bh[3]);
                }
            }
        }
        // dM GEMM: ldmT(K(c)) * WG re-split, accumulate into pre-scaled m0
        {
            float s63 = ((float*)(sm + S_SC))[par];
            #pragma unroll
            for (int j = 0; j < 4; j++)
                #pragma unroll
                for (int e = 0; e < 4; e++) m0[j][e] *= s63;
            const uint32_t ktB = sb + kbH + laneT + ((uint32_t)(wr * 16) << 1);
            #pragma unroll
            for (int ks = 0; ks < 4; ks++) {
                uint32_t kh4[4], kl4[4];
                ldmT(kh4, ktB + (uint32_t)(ks * 16) * 272u);
                ldmT(kl4, ktB + 17408u + (uint32_t)(ks * 16) * 272u);
                int sA0 = ks * 16 + 2 * tig;
                float wg0 = WGs[sA0], wg1 = WGs[sA0 + 1];
                float wg2 = WGs[sA0 + 8], wg3 = WGs[sA0 + 9];
                uint32_t ka[4], kb2[4];
                #pragma unroll
                for (int p = 0; p < 4; p++) {
                    float sw0 = (p < 2) ? wg0 : wg2;
                    float sw1 = (p < 2) ? wg1 : wg3;
                    __nv_bfloat162 H = *(__nv_bfloat162*)&kh4[p];
                    __nv_bfloat162 L = *(__nv_bfloat162*)&kl4[p];
                    float v0 = (__bfloat162float(H.x) + __bfloat162float(L.x)) * sw0;
                    float v1 = (__bfloat162float(H.y) + __bfloat162float(L.y)) * sw1;
                    sp2(v0, v1, ka[p], kb2[p]);
                }
                #pragma unroll
                for (int jj = 0; jj < 2; jj++) {
                    uint32_t bh[4], bl[4];
                    uint32_t vB = sb + S_VH + (uint32_t)(wc * 32 + 16 * jj) * 144u + ks * 32 + laneB144x4;
                    ldmB4(bh, vB); ldmB4(bl, vB + (S_VL - S_VH));
                    mma16(m0[2*jj],   ka, bh[0], bh[1]); mma16(m0[2*jj],   ka, bl[0], bl[1]); mma16(m0[2*jj],   kb2, bh[0], bh[1]);
                    mma16(m0[2*jj+1], ka, bh[2], bh[3]); mma16(m0[2*jj+1], ka, bl[2], bl[3]); mma16(m0[2*jj+1], kb2, bh[2], bh[3]);
                }
            }
        }
        // S(c+1) GEMM (q(c+1) frags x K(c+1) in nb buffer)
        #pragma unroll
        for (int j = 0; j < 2; j++)
            #pragma unroll
            for (int e = 0; e < 4; e++) sS[j][e] = 0.f;
        if (sact && c + 1 < NCH) {
            const float* qr1 = q + (tb0 + CC + (size_t)(rt * 16 + gid)) * 128 + 2 * tig;
            const uint32_t col = (uint32_t)(ct * 16);
            #pragma unroll
            for (int ks = 0; ks < 8; ks++) {
                uint32_t qa[4], ql[4];
                float2 f0 = *(const float2*)(qr1 + ks * 16);
                float2 f1 = *(const float2*)(qr1 + 8 * 128 + ks * 16);
                float2 f2 = *(const float2*)(qr1 + ks * 16 + 8);
                float2 f3 = *(const float2*)(qr1 + 8 * 128 + ks * 16 + 8);
                sp2(f0.x, f0.y, qa[0], ql[0]); sp2(f1.x, f1.y, qa[1], ql[1]);
                sp2(f2.x, f2.y, qa[2], ql[2]); sp2(f3.x, f3.y, qa[3], ql[3]);
                uint32_t bh[4], bl[4];
                uint32_t kB = sb + nbH + col * 272u + ks * 32 + laneB272x4;
                ldmB4(bh, kB); ldmB4(bl, kB + 17408u);
                mma16(sS[0], qa, bh[0], bh[1]); mma16(sS[0], qa, bl[0], bl[1]); mma16(sS[0], ql, bh[0], bh[1]);
                mma16(sS[1], qa, bh[2], bh[3]); mma16(sS[1], qa, bl[2], bl[3]); mma16(sS[1], ql, bh[2], bh[3]);
            }
        }
        // readout r = EG_t * QM0 + AV
        {
            int t0 = rt * 16 + gid, t1 = t0 + 8;
            float e0 = EGs[t0], e1 = EGs[t1];
            #pragma unroll
            for (int j = 0; j < 2; j++) {
                int n = ct * 16 + 8 * j + 2 * tig;
                float2 o0 = make_float2(fmaf(e0, sQ[j][0], sA[j][0]), fmaf(e0, sQ[j][1], sA[j][1]));
                float2 o1 = make_float2(fmaf(e1, sQ[j][2], sA[j][2]), fmaf(e1, sQ[j][3], sA[j][3]));
                *(float2*)(out + (tb0 + t0) * 128 + vh * 64 + n) = o0;
                *(float2*)(out + (tb0 + t1) * 128 + vh * 64 + n) = o1;
            }
        }
        // M^T(c+1) write from updated m0 regs
        #pragma unroll
        for (int j = 0; j < 4; j++) {
            int n = wc * 32 + 8 * j + 2 * tig;
            #pragma unroll
            for (int e = 0; e < 4; e++) {
                int nn = n + (e & 1), m = (e < 2) ? mr0 : mr1;
                __nv_bfloat16 h, l; spl(m0[j][e], h, l);
                uint32_t o = (uint32_t)nn * 272u + ((uint32_t)m << 1);
                *(__nv_bfloat16*)(sm + S_MH + o) = h;
                *(__nv_bfloat16*)(sm + S_ML + o) = l;
            }
        }
        __syncthreads();   // sync B
    }
}

extern "C" void kernel_launch(void* const* d_in, const int* in_sizes, int n_in,
                              void* d_out, int out_size)
{
    (void)in_sizes; (void)n_in; (void)out_size;
    cudaFuncSetAttribute(lmm_hmma, cudaFuncAttributeMaxDynamicSharedMemorySize, SMEMB);
    lmm_hmma<<<128, NT, SMEMB>>>((const float*)d_in[0], (const float*)d_in[1],
                                 (const float*)d_in[2], (const float*)d_in[3],
                                 (const float*)d_in[4], (const float*)d_in[5],
                                 (const float*)d_in[6], (float*)d_out);
}

// round 15
// speedup vs baseline: 1.3799x; 1.3799x over previous
#include <cuda_runtime.h>
#include <cuda_bf16.h>
#include <cstdint>

#define TT 2048
#define CC 64
#define NCH 32
#define NT 512

// K tiles [64s x 128m] stride 272, double-buffered. MT [64n x 128m] 272.
// VT [64n x 64s] 144. A [64t x 64s] 144. Scalars parity double-buffered (2x64 f32).
#define S_K0H 0
#define S_K0L 17408
#define S_K1H 34816
#define S_K1L 52224
#define S_MH  69632
#define S_ML  87040
#define S_VH  104448
#define S_VL  113664
#define S_AH  122880
#define S_AL  132096
#define S_G   141312
#define S_WS  141824
#define S_WG  142336
#define S_EG  142848
#define S_SC  143360
#define SMEMB 143392

static __device__ __forceinline__ uint32_t su32(const void* p) {
    uint32_t a;
    asm("{ .reg .u64 t; cvta.to.shared.u64 t, %1; cvt.u32.u64 %0, t; }" : "=r"(a) : "l"(p));
    return a;
}
static __device__ __forceinline__ void ldmA(uint32_t a[4], uint32_t addr) {
    asm volatile("ldmatrix.sync.aligned.m8n8.x4.shared.b16 {%0,%1,%2,%3}, [%4];"
        : "=r"(a[0]), "=r"(a[1]), "=r"(a[2]), "=r"(a[3]) : "r"(addr));
}
static __device__ __forceinline__ void ldmB4(uint32_t b[4], uint32_t addr) {
    asm volatile("ldmatrix.sync.aligned.m8n8.x4.shared.b16 {%0,%1,%2,%3}, [%4];"
        : "=r"(b[0]), "=r"(b[1]), "=r"(b[2]), "=r"(b[3]) : "r"(addr));
}
static __device__ __forceinline__ void ldmT(uint32_t a[4], uint32_t addr) {
    asm volatile("ldmatrix.sync.aligned.m8n8.x4.trans.shared.b16 {%0,%1,%2,%3}, [%4];"
        : "=r"(a[0]), "=r"(a[1]), "=r"(a[2]), "=r"(a[3]) : "r"(addr));
}
static __device__ __forceinline__ void mma16(float c[4], const uint32_t a[4], uint32_t b0, uint32_t b1) {
    asm volatile("mma.sync.aligned.m16n8k16.row.col.f32.bf16.bf16.f32 "
        "{%0,%1,%2,%3}, {%4,%5,%6,%7}, {%8,%9}, {%0,%1,%2,%3};"
        : "+f"(c[0]), "+f"(c[1]), "+f"(c[2]), "+f"(c[3])
        : "r"(a[0]), "r"(a[1]), "r"(a[2]), "r"(a[3]), "r"(b0), "r"(b1));
}
static __device__ __forceinline__ void spl(float x, __nv_bfloat16& h, __nv_bfloat16& l) {
    h = __float2bfloat16_rn(x);
    l = __float2bfloat16_rn(x - __bfloat162float(h));
}
static __device__ __forceinline__ void sp2(float x0, float x1, uint32_t& hi, uint32_t& lo) {
    __nv_bfloat16 h0, l0, h1, l1;
    spl(x0, h0, l0); spl(x1, h1, l1);
    hi = (uint32_t)__bfloat16_as_ushort(h0) | ((uint32_t)__bfloat16_as_ushort(h1) << 16);
    lo = (uint32_t)__bfloat16_as_ushort(l0) | ((uint32_t)__bfloat16_as_ushort(l1) << 16);
}
// exp2(x) for x <= 0, FFMA-only
static __device__ __forceinline__ float ex2n(float x) {
    float xc = fmaxf(x, -150.f);
    float xf = floorf(xc);
    float f  = xc - xf;
    float p = 1.54035e-4f;
    p = fmaf(p, f, 1.3335581e-3f);
    p = fmaf(p, f, 9.6181291e-3f);
    p = fmaf(p, f, 5.5504109e-2f);
    p = fmaf(p, f, 2.4022651e-1f);
    p = fmaf(p, f, 6.9314718e-1f);
    p = fmaf(p, f, 1.0f);
    float r = __int_as_float(__float_as_int(p) + (((int)xf) << 23));
    return (xc <= -126.f) ? 0.f : r;
}

__global__ void __launch_bounds__(NT, 1)
lmm_hmma(const float* __restrict__ q, const float* __restrict__ kk,
         const float* __restrict__ v, const float* __restrict__ alpha,
         const float* __restrict__ rho, const float* __restrict__ lam,
         const float* __restrict__ init, float* __restrict__ out)
{
    extern __shared__ char sm[];
    const uint32_t sb = su32(sm);
    const int tid = threadIdx.x, warp = tid >> 5, lane = tid & 31;
    const int gid = lane >> 2, tig = lane & 3;
    const int b = blockIdx.x >> 1, vh = blockIdx.x & 1;
    const int rt = warp >> 2, ct = warp & 3;   // S / QM0 / AV: 16x16 tile (rt, ct)
    const int wr = warp >> 1, wc = warp & 1;   // dM / M0: rows wr*16.., cols wc*32..
    const bool sact = (ct <= rt);

    const uint32_t laneA144 = (uint32_t)(lane & 15) * 144u + (uint32_t)((lane >> 4) << 4);
    const uint32_t laneB272x4 = (uint32_t)(lane & 7) * 272u + (uint32_t)(((lane >> 3) & 1) << 4)
                              + (uint32_t)(lane >> 4) * (8u * 272u);
    const uint32_t laneB144x4 = (uint32_t)(lane & 7) * 144u + (uint32_t)(((lane >> 3) & 1) << 4)
                              + (uint32_t)(lane >> 4) * (8u * 144u);
    const uint32_t laneT = ((uint32_t)(lane & 7) + (uint32_t)((lane >> 4) << 3)) * 272u
                         + (uint32_t)(lane & 8) * 2u;

    // scalars for the chunk starting at tbX -> parity buffer parX (warp 0 only)
    auto do_scalars = [&](size_t tbX, int parX) {
        float* Gp  = (float*)(sm + S_G)  + parX * 64;
        float* WSp = (float*)(sm + S_WS) + parX * 64;
        float* WGp = (float*)(sm + S_WG) + parX * 64;
        float* EGp = (float*)(sm + S_EG) + parX * 64;
        float x = log2f(fmaxf(lam[tbX + lane], 1e-37f));
        #pragma unroll
        for (int o = 1; o < 32; o <<= 1) { float y = __shfl_up_sync(~0u, x, o); if (lane >= o) x += y; }
        float tot = __shfl_sync(~0u, x, 31);
        float y2 = log2f(fmaxf(lam[tbX + 32 + lane], 1e-37f));
        #pragma unroll
        for (int o = 1; o < 32; o <<= 1) { float y = __shfl_up_sync(~0u, y2, o); if (lane >= o) y2 += y; }
        float g2 = tot + y2;
        float g63 = __shfl_sync(~0u, g2, 31);
        float w0 = rho[tbX + lane] * alpha[tbX + lane];
        float w1 = rho[tbX + 32 + lane] * alpha[tbX + 32 + lane];
        Gp[lane] = x;            Gp[32 + lane] = g2;
        WSp[lane] = w0;          WSp[32 + lane] = w1;
        EGp[lane] = ex2n(x);     EGp[32 + lane] = ex2n(g2);
        WGp[lane] = ex2n(g63 - x) * w0;
        WGp[32 + lane] = ex2n(g63 - g2) * w1;
        if (lane == 31) ((float*)(sm + S_SC))[parX] = ex2n(g63);
    };

    // ---- M0 in registers: warp owns rows [wr*16,+16), cols [wc*32,+32) ----
    const int mr0 = wr * 16 + gid, mr1 = mr0 + 8;
    float m0[4][4];
    {
        const float* ip = init + (size_t)b * 16384 + vh * 64;
        #pragma unroll
        for (int j = 0; j < 4; j++) {
            int n = wc * 32 + 8 * j + 2 * tig;
            float2 f0 = *(const float2*)(ip + (size_t)mr0 * 128 + n);
            float2 f1 = *(const float2*)(ip + (size_t)mr1 * 128 + n);
            m0[j][0] = f0.x; m0[j][1] = f0.y; m0[j][2] = f1.x; m0[j][3] = f1.y;
        }
    }
    // initial M^T tiles from regs
    #pragma unroll
    for (int j = 0; j < 4; j++) {
        int n = wc * 32 + 8 * j + 2 * tig;
        #pragma unroll
        for (int e = 0; e < 4; e++) {
            int nn = n + (e & 1), m = (e < 2) ? mr0 : mr1;
            __nv_bfloat16 h, l; spl(m0[j][e], h, l);
            uint32_t o = (uint32_t)nn * 272u + ((uint32_t)m << 1);
            *(__nv_bfloat16*)(sm + S_MH + o) = h;
            *(__nv_bfloat16*)(sm + S_ML + o) = l;
        }
    }
    // K(0) tiles -> buf0
    {
        const size_t t0 = (size_t)b * TT;
        for (int i = tid; i < 2048; i += NT) {
            int t = i >> 5, c4 = (i & 31) << 2;
            uint32_t o = (uint32_t)t * 272u + (uint32_t)(c4 << 1);
            float4 f = *(const float4*)(kk + (t0 + t) * 128 + c4);
            uint32_t h0, l0, h1, l1;
            sp2(f.x, f.y, h0, l0); sp2(f.z, f.w, h1, l1);
            *(uint32_t*)(sm + S_K0H + o) = h0; *(uint32_t*)(sm + S_K0H + o + 4) = h1;
            *(uint32_t*)(sm + S_K0L + o) = l0; *(uint32_t*)(sm + S_K0L + o + 4) = l1;
        }
    }
    if (warp == 0) do_scalars((size_t)b * TT, 0);
    // V(0) prefetch
    float vreg[8];
    #pragma unroll
    for (int ii = 0; ii < 8; ii++) {
        int i = tid + ii * NT;
        vreg[ii] = v[((size_t)b * TT + (size_t)(i >> 6)) * 128 + vh * 64 + (i & 63)];
    }
    __syncthreads();   // prologue: K(0), M^T(0), scalars(0) visible

    for (int c = 0; c < NCH; c++) {
        const size_t tb0 = (size_t)b * TT + (size_t)c * CC;
        const int par = c & 1;
        const uint32_t kbH = par ? S_K1H : S_K0H;     // K(c)
        const uint32_t nbH = par ? S_K0H : S_K1H;     // K(c+1)
        float* Gs  = (float*)(sm + S_G)  + par * 64;
        float* WSs = (float*)(sm + S_WS) + par * 64;
        float* WGs = (float*)(sm + S_WG) + par * 64;
        float* EGs = (float*)(sm + S_EG) + par * 64;

        // ---- GEMM1: S = Qfrag K^T (ct<=rt) and QM0 = Qfrag M^T (K=128) ----
        float sS[2][4], sQ[2][4];
        #pragma unroll
        for (int j = 0; j < 2; j++)
            #pragma unroll
            for (int e = 0; e < 4; e++) { sS[j][e] = 0.f; sQ[j][e] = 0.f; }
        {
            const float* qr0 = q + (tb0 + (size_t)(rt * 16 + gid)) * 128 + 2 * tig;
            const uint32_t col = (uint32_t)(ct * 16);
            #pragma unroll
            for (int ks = 0; ks < 8; ks++) {
                uint32_t qa[4], ql[4];
                {
                    float2 f0 = *(const float2*)(qr0 + ks * 16);
                    float2 f1 = *(const float2*)(qr0 + 8 * 128 + ks * 16);
                    float2 f2 = *(const float2*)(qr0 + ks * 16 + 8);
                    float2 f3 = *(const float2*)(qr0 + 8 * 128 + ks * 16 + 8);
                    sp2(f0.x, f0.y, qa[0], ql[0]);
                    sp2(f1.x, f1.y, qa[1], ql[1]);
                    sp2(f2.x, f2.y, qa[2], ql[2]);
                    sp2(f3.x, f3.y, qa[3], ql[3]);
                }
                if (sact) {
                    uint32_t bh[4], bl[4];
                    uint32_t kB = sb + kbH + col * 272u + ks * 32 + laneB272x4;
                    ldmB4(bh, kB); ldmB4(bl, kB + 17408u);
                    mma16(sS[0], qa, bh[0], bh[1]); mma16(sS[0], qa, bl[0], bl[1]); mma16(sS[0], ql, bh[0], bh[1]);
                    mma16(sS[1], qa, bh[2], bh[3]); mma16(sS[1], qa, bl[2], bl[3]); mma16(sS[1], ql, bh[2], bh[3]);
                }
                {
                    uint32_t bh[4], bl[4];
                    uint32_t mB = sb + S_MH + col * 272u + ks * 32 + laneB272x4;
                    ldmB4(bh, mB); ldmB4(bl, mB + (S_ML - S_MH));
                    mma16(sQ[0], qa, bh[0], bh[1]); mma16(sQ[0], qa, bl[0], bl[1]); mma16(sQ[0], ql, bh[0], bh[1]);
                    mma16(sQ[1], qa, bh[2], bh[3]); mma16(sQ[1], qa, bl[2], bl[3]); mma16(sQ[1], ql, bh[2], bh[3]);
                }
            }
        }
        // ---- A build (lower triangle) ----
        if (sact) {
            int t0 = rt * 16 + gid, t1 = t0 + 8;
            float g0 = Gs[t0], g1 = Gs[t1];
            #pragma unroll
            for (int j = 0; j < 2; j++) {
                int s0 = ct * 16 + 8 * j + 2 * tig, s1 = s0 + 1;
                float gs0 = Gs[s0], gs1 = Gs[s1], w0 = WSs[s0], w1 = WSs[s1];
                float a00 = (t0 >= s0) ? ex2n(g0 - gs0) * w0 * sS[j][0] : 0.f;
                float a01 = (t0 >= s1) ? ex2n(g0 - gs1) * w1 * sS[j][1] : 0.f;
                float a10 = (t1 >= s0) ? ex2n(g1 - gs0) * w0 * sS[j][2] : 0.f;
                float a11 = (t1 >= s1) ? ex2n(g1 - gs1) * w1 * sS[j][3] : 0.f;
                uint32_t hi, lo;
                sp2(a00, a01, hi, lo);
                uint32_t o = (uint32_t)t0 * 144u + (uint32_t)(s0 << 1);
                *(uint32_t*)(sm + S_AH + o) = hi; *(uint32_t*)(sm + S_AL + o) = lo;
                sp2(a10, a11, hi, lo);
                o = (uint32_t)t1 * 144u + (uint32_t)(s0 << 1);
                *(uint32_t*)(sm + S_AH + o) = hi; *(uint32_t*)(sm + S_AL + o) = lo;
            }
        }
        // ---- V^T(c) store from regs [64n x 64s] ----
        #pragma unroll
        for (int ii = 0; ii < 8; ii++) {
            int i = tid + ii * NT;
            int s = i >> 6, n = i & 63;
            __nv_bfloat16 h, l; spl(vreg[ii], h, l);
            uint32_t o = (uint32_t)n * 144u + (uint32_t)(s << 1);
            *(__nv_bfloat16*)(sm + S_VH + o) = h;
            *(__nv_bfloat16*)(sm + S_VL + o) = l;
        }
        __syncthreads();   // sync A: A(c) + V^T(c) visible

        // ---- scalars(c+1) (warp 0; overlaps with other warps' GEMM2 below) ----
        if (warp == 0 && c + 1 < NCH) do_scalars(tb0 + CC, par ^ 1);

        // ---- K(c+1) + V(c+1) prefetch to regs ----
        const size_t tb1 = tb0 + ((c + 1 < NCH) ? CC : 0);
        float4 kreg[4];
        #pragma unroll
        for (int ii = 0; ii < 4; ii++) {
            int i = tid + ii * NT;
            kreg[ii] = *(const float4*)(kk + (tb1 + (size_t)(i >> 5)) * 128 + ((i & 31) << 2));
        }
        #pragma unroll
        for (int ii = 0; ii < 8; ii++) {
            int i = tid + ii * NT;
            vreg[ii] = v[(tb1 + (size_t)(i >> 6)) * 128 + vh * 64 + (i & 63)];
        }

        // ---- GEMM2: AV (ks<=rt) ; dM mma directly into pre-scaled m0 regs ----
        float sA[2][4];
        #pragma unroll
        for (int j = 0; j < 2; j++)
            #pragma unroll
            for (int e = 0; e < 4; e++) sA[j][e] = 0.f;
        {
            const uint32_t ahB = sb + S_AH + (uint32_t)(rt * 16) * 144u + laneA144;
            #pragma unroll
            for (int ks = 0; ks < 4; ks++) {
                if (ks <= rt) {
                    uint32_t aa[4], al[4];
                    ldmA(aa, ahB + ks * 32); ldmA(al, ahB + (S_AL - S_AH) + ks * 32);
                    uint32_t bh[4], bl[4];
                    uint32_t vB = sb + S_VH + (uint32_t)(ct * 16) * 144u + ks * 32 + laneB144x4;
                    ldmB4(bh, vB); ldmB4(bl, vB + (S_VL - S_VH));
                    mma16(sA[0], aa, bh[0], bh[1]); mma16(sA[0], aa, bl[0], bl[1]); mma16(sA[0], al, bh[0], bh[1]);
                    mma16(sA[1], aa, bh[2], bh[3]); mma16(sA[1], aa, bl[2], bl[3]); mma16(sA[1], al, bh[2], bh[3]);
                }
            }
            float s63 = ((float*)(sm + S_SC))[par];
            #pragma unroll
            for (int j = 0; j < 4; j++)
                #pragma unroll
                for (int e = 0; e < 4; e++) m0[j][e] *= s63;
            const uint32_t ktB = sb + kbH + laneT + ((uint32_t)(wr * 16) << 1);
            #pragma unroll
            for (int ks = 0; ks < 4; ks++) {
                uint32_t kh4[4], kl4[4];
                ldmT(kh4, ktB + (uint32_t)(ks * 16) * 272u);
                ldmT(kl4, ktB + 17408u + (uint32_t)(ks * 16) * 272u);
                int sA0 = ks * 16 + 2 * tig;
                float wg0 = WGs[sA0], wg1 = WGs[sA0 + 1];
                float wg2 = WGs[sA0 + 8], wg3 = WGs[sA0 + 9];
                uint32_t ka[4], kb2[4];
                #pragma unroll
                for (int p = 0; p < 4; p++) {
                    float sw0 = (p < 2) ? wg0 : wg2;
                    float sw1 = (p < 2) ? wg1 : wg3;
                    __nv_bfloat162 H = *(__nv_bfloat162*)&kh4[p];
                    __nv_bfloat162 L = *(__nv_bfloat162*)&kl4[p];
                    float v0 = (__bfloat162float(H.x) + __bfloat162float(L.x)) * sw0;
                    float v1 = (__bfloat162float(H.y) + __bfloat162float(L.y)) * sw1;
                    sp2(v0, v1, ka[p], kb2[p]);
                }
                #pragma unroll
                for (int jj = 0; jj < 2; jj++) {
                    uint32_t bh[4], bl[4];
                    uint32_t vB = sb + S_VH + (uint32_t)(wc * 32 + 16 * jj) * 144u + ks * 32 + laneB144x4;
                    ldmB4(bh, vB); ldmB4(bl, vB + (S_VL - S_VH));
                    mma16(m0[2*jj],   ka, bh[0], bh[1]); mma16(m0[2*jj],   ka, bl[0], bl[1]); mma16(m0[2*jj],   kb2, bh[0], bh[1]);
                    mma16(m0[2*jj+1], ka, bh[2], bh[3]); mma16(m0[2*jj+1], ka, bl[2], bl[3]); mma16(m0[2*jj+1], kb2, bh[2], bh[3]);
                }
            }
        }
        // ---- readout r = EG_t * QM0 + AV ----
        {
            int t0 = rt * 16 + gid, t1 = t0 + 8;
            float e0 = EGs[t0], e1 = EGs[t1];
            #pragma unroll
            for (int j = 0; j < 2; j++) {
                int n = ct * 16 + 8 * j + 2 * tig;
                float2 o0 = make_float2(fmaf(e0, sQ[j][0], sA[j][0]), fmaf(e0, sQ[j][1], sA[j][1]));
                float2 o1 = make_float2(fmaf(e1, sQ[j][2], sA[j][2]), fmaf(e1, sQ[j][3], sA[j][3]));
                *(float2*)(out + (tb0 + t0) * 128 + vh * 64 + n) = o0;
                *(float2*)(out + (tb0 + t1) * 128 + vh * 64 + n) = o1;
            }
        }
        // ---- K(c+1) STS ----
        #pragma unroll
        for (int ii = 0; ii < 4; ii++) {
            int i = tid + ii * NT;
            int t = i >> 5, c4 = (i & 31) << 2;
            uint32_t o = (uint32_t)t * 272u + (uint32_t)(c4 << 1);
            uint32_t h0, l0, h1, l1;
            sp2(kreg[ii].x, kreg[ii].y, h0, l0); sp2(kreg[ii].z, kreg[ii].w, h1, l1);
            *(uint32_t*)(sm + nbH + o) = h0; *(uint32_t*)(sm + nbH + o + 4) = h1;
            *(uint32_t*)(sm + nbH + 17408u + o) = l0; *(uint32_t*)(sm + nbH + 17408u + o + 4) = l1;
        }
        // ---- M^T(c+1) from updated m0 regs ----
        #pragma unroll
        for (int j = 0; j < 4; j++) {
            int n = wc * 32 + 8 * j + 2 * tig;
            #pragma unroll
            for (int e = 0; e < 4; e++) {
                int nn = n + (e & 1), m = (e < 2) ? mr0 : mr1;
                __nv_bfloat16 h, l; spl(m0[j][e], h, l);
                uint32_t o = (uint32_t)nn * 272u + ((uint32_t)m << 1);
                *(__nv_bfloat16*)(sm + S_MH + o) = h;
                *(__nv_bfloat16*)(sm + S_ML + o) = l;
            }
        }
        __syncthreads();   // sync B: K(c+1), M^T(c+1), scalars(c+1) visible
    }
}

extern "C" void kernel_launch(void* const* d_in, const int* in_sizes, int n_in,
                              void* d_out, int out_size)
{
    (void)in_sizes; (void)n_in; (void)out_size;
    cudaFuncSetAttribute(lmm_hmma, cudaFuncAttributeMaxDynamicSharedMemorySize, SMEMB);
    lmm_hmma<<<128, NT, SMEMB>>>((const float*)d_in[0], (const float*)d_in[1],
                                 (const float*)d_in[2], (const float*)d_in[3],
                                 (const float*)d_in[4], (const float*)d_in[5],
                                 (const float*)d_in[6], (float*)d_out);
}

// round 16
// speedup vs baseline: 1.5914x; 1.1533x over previous
#include <cuda_runtime.h>
#include <cuda_bf16.h>
#include <cstdint>

#define TT 2048
#define CC 64
#define NCH 32
#define NT 512

// K tiles [64s x 128m] stride 272, double-buffered. Q tiles same, double-buffered.
// MT [64n x 128m] 272. VT [64n x 64s] 144. A [64t x 64s] 144. Scalars parity 2x64.
#define S_K0H 0
#define S_K0L 17408
#define S_K1H 34816
#define S_K1L 52224
#define S_MH  69632
#define S_ML  87040
#define S_VH  104448
#define S_VL  113664
#define S_AH  122880
#define S_AL  132096
#define S_G   141312
#define S_WS  141824
#define S_WG  142336
#define S_EG  142848
#define S_SC  143360
#define S_Q0H 143392
#define S_Q0L 160800
#define S_Q1H 178208
#define S_Q1L 195616
#define SMEMB 213024

static __device__ __forceinline__ uint32_t su32(const void* p) {
    uint32_t a;
    asm("{ .reg .u64 t; cvta.to.shared.u64 t, %1; cvt.u32.u64 %0, t; }" : "=r"(a) : "l"(p));
    return a;
}
static __device__ __forceinline__ void ldmA(uint32_t a[4], uint32_t addr) {
    asm volatile("ldmatrix.sync.aligned.m8n8.x4.shared.b16 {%0,%1,%2,%3}, [%4];"
        : "=r"(a[0]), "=r"(a[1]), "=r"(a[2]), "=r"(a[3]) : "r"(addr));
}
static __device__ __forceinline__ void ldmB4(uint32_t b[4], uint32_t addr) {
    asm volatile("ldmatrix.sync.aligned.m8n8.x4.shared.b16 {%0,%1,%2,%3}, [%4];"
        : "=r"(b[0]), "=r"(b[1]), "=r"(b[2]), "=r"(b[3]) : "r"(addr));
}
static __device__ __forceinline__ void ldmT(uint32_t a[4], uint32_t addr) {
    asm volatile("ldmatrix.sync.aligned.m8n8.x4.trans.shared.b16 {%0,%1,%2,%3}, [%4];"
        : "=r"(a[0]), "=r"(a[1]), "=r"(a[2]), "=r"(a[3]) : "r"(addr));
}
static __device__ __forceinline__ void mma16(float c[4], const uint32_t a[4], uint32_t b0, uint32_t b1) {
    asm volatile("mma.sync.aligned.m16n8k16.row.col.f32.bf16.bf16.f32 "
        "{%0,%1,%2,%3}, {%4,%5,%6,%7}, {%8,%9}, {%0,%1,%2,%3};"
        : "+f"(c[0]), "+f"(c[1]), "+f"(c[2]), "+f"(c[3])
        : "r"(a[0]), "r"(a[1]), "r"(a[2]), "r"(a[3]), "r"(b0), "r"(b1));
}
static __device__ __forceinline__ void spl(float x, __nv_bfloat16& h, __nv_bfloat16& l) {
    h = __float2bfloat16_rn(x);
    l = __float2bfloat16_rn(x - __bfloat162float(h));
}
static __device__ __forceinline__ void sp2(float x0, float x1, uint32_t& hi, uint32_t& lo) {
    __nv_bfloat16 h0, l0, h1, l1;
    spl(x0, h0, l0); spl(x1, h1, l1);
    hi = (uint32_t)__bfloat16_as_ushort(h0) | ((uint32_t)__bfloat16_as_ushort(h1) << 16);
    lo = (uint32_t)__bfloat16_as_ushort(l0) | ((uint32_t)__bfloat16_as_ushort(l1) << 16);
}
// exp2(x) for x <= 0, FFMA-only
static __device__ __forceinline__ float ex2n(float x) {
    float xc = fmaxf(x, -150.f);
    float xf = floorf(xc);
    float f  = xc - xf;
    float p = 1.54035e-4f;
    p = fmaf(p, f, 1.3335581e-3f);
    p = fmaf(p, f, 9.6181291e-3f);
    p = fmaf(p, f, 5.5504109e-2f);
    p = fmaf(p, f, 2.4022651e-1f);
    p = fmaf(p, f, 6.9314718e-1f);
    p = fmaf(p, f, 1.0f);
    float r = __int_as_float(__float_as_int(p) + (((int)xf) << 23));
    return (xc <= -126.f) ? 0.f : r;
}

__global__ void __launch_bounds__(NT, 1)
lmm_hmma(const float* __restrict__ q, const float* __restrict__ kk,
         const float* __restrict__ v, const float* __restrict__ alpha,
         const float* __restrict__ rho, const float* __restrict__ lam,
         const float* __restrict__ init, float* __restrict__ out)
{
    extern __shared__ char sm[];
    const uint32_t sb = su32(sm);
    const int tid = threadIdx.x, warp = tid >> 5, lane = tid & 31;
    const int gid = lane >> 2, tig = lane & 3;
    const int b = blockIdx.x >> 1, vh = blockIdx.x & 1;
    const int rt = warp >> 2, ct = warp & 3;
    const int wr = warp >> 1, wc = warp & 1;
    const bool sact = (ct <= rt);

    const uint32_t laneA272 = (uint32_t)(lane & 15) * 272u + (uint32_t)((lane >> 4) << 4);
    const uint32_t laneA144 = (uint32_t)(lane & 15) * 144u + (uint32_t)((lane >> 4) << 4);
    const uint32_t laneB272x4 = (uint32_t)(lane & 7) * 272u + (uint32_t)(((lane >> 3) & 1) << 4)
                              + (uint32_t)(lane >> 4) * (8u * 272u);
    const uint32_t laneB144x4 = (uint32_t)(lane & 7) * 144u + (uint32_t)(((lane >> 3) & 1) << 4)
                              + (uint32_t)(lane >> 4) * (8u * 144u);
    const uint32_t laneT = ((uint32_t)(lane & 7) + (uint32_t)((lane >> 4) << 3)) * 272u
                         + (uint32_t)(lane & 8) * 2u;

    auto do_scalars = [&](size_t tbX, int parX) {
        float* Gp  = (float*)(sm + S_G)  + parX * 64;
        float* WSp = (float*)(sm + S_WS) + parX * 64;
        float* WGp = (float*)(sm + S_WG) + parX * 64;
        float* EGp = (float*)(sm + S_EG) + parX * 64;
        float x = log2f(fmaxf(lam[tbX + lane], 1e-37f));
        #pragma unroll
        for (int o = 1; o < 32; o <<= 1) { float y = __shfl_up_sync(~0u, x, o); if (lane >= o) x += y; }
        float tot = __shfl_sync(~0u, x, 31);
        float y2 = log2f(fmaxf(lam[tbX + 32 + lane], 1e-37f));
        #pragma unroll
        for (int o = 1; o < 32; o <<= 1) { float y = __shfl_up_sync(~0u, y2, o); if (lane >= o) y2 += y; }
        float g2 = tot + y2;
        float g63 = __shfl_sync(~0u, g2, 31);
        float w0 = rho[tbX + lane] * alpha[tbX + lane];
        float w1 = rho[tbX + 32 + lane] * alpha[tbX + 32 + lane];
        Gp[lane] = x;            Gp[32 + lane] = g2;
        WSp[lane] = w0;          WSp[32 + lane] = w1;
        EGp[lane] = ex2n(x);     EGp[32 + lane] = ex2n(g2);
        WGp[lane] = ex2n(g63 - x) * w0;
        WGp[32 + lane] = ex2n(g63 - g2) * w1;
        if (lane == 31) ((float*)(sm + S_SC))[parX] = ex2n(g63);
    };

    // ---- M0 in registers ----
    const int mr0 = wr * 16 + gid, mr1 = mr0 + 8;
    float m0[4][4];
    {
        const float* ip = init + (size_t)b * 16384 + vh * 64;
        #pragma unroll
        for (int j = 0; j < 4; j++) {
            int n = wc * 32 + 8 * j + 2 * tig;
            float2 f0 = *(const float2*)(ip + (size_t)mr0 * 128 + n);
            float2 f1 = *(const float2*)(ip + (size_t)mr1 * 128 + n);
            m0[j][0] = f0.x; m0[j][1] = f0.y; m0[j][2] = f1.x; m0[j][3] = f1.y;
        }
    }
    #pragma unroll
    for (int j = 0; j < 4; j++) {
        int n = wc * 32 + 8 * j + 2 * tig;
        #pragma unroll
        for (int e = 0; e < 4; e++) {
            int nn = n + (e & 1), m = (e < 2) ? mr0 : mr1;
            __nv_bfloat16 h, l; spl(m0[j][e], h, l);
            uint32_t o = (uint32_t)nn * 272u + ((uint32_t)m << 1);
            *(__nv_bfloat16*)(sm + S_MH + o) = h;
            *(__nv_bfloat16*)(sm + S_ML + o) = l;
        }
    }
    // K(0) and Q(0) tiles -> buf0
    {
        const size_t t0 = (size_t)b * TT;
        for (int i = tid; i < 2048; i += NT) {
            int t = i >> 5, c4 = (i & 31) << 2;
            uint32_t o = (uint32_t)t * 272u + (uint32_t)(c4 << 1);
            float4 f = *(const float4*)(kk + (t0 + t) * 128 + c4);
            uint32_t h0, l0, h1, l1;
            sp2(f.x, f.y, h0, l0); sp2(f.z, f.w, h1, l1);
            *(uint32_t*)(sm + S_K0H + o) = h0; *(uint32_t*)(sm + S_K0H + o + 4) = h1;
            *(uint32_t*)(sm + S_K0L + o) = l0; *(uint32_t*)(sm + S_K0L + o + 4) = l1;
            f = *(const float4*)(q + (t0 + t) * 128 + c4);
            sp2(f.x, f.y, h0, l0); sp2(f.z, f.w, h1, l1);
            *(uint32_t*)(sm + S_Q0H + o) = h0; *(uint32_t*)(sm + S_Q0H + o + 4) = h1;
            *(uint32_t*)(sm + S_Q0L + o) = l0; *(uint32_t*)(sm + S_Q0L + o + 4) = l1;
        }
    }
    if (warp == 0) do_scalars((size_t)b * TT, 0);
    float vreg[8];
    #pragma unroll
    for (int ii = 0; ii < 8; ii++) {
        int i = tid + ii * NT;
        vreg[ii] = v[((size_t)b * TT + (size_t)(i >> 6)) * 128 + vh * 64 + (i & 63)];
    }
    __syncthreads();   // prologue: K(0), Q(0), M^T(0), scalars(0) visible

    for (int c = 0; c < NCH; c++) {
        const size_t tb0 = (size_t)b * TT + (size_t)c * CC;
        const int par = c & 1;
        const uint32_t kbH = par ? S_K1H : S_K0H;
        const uint32_t nbH = par ? S_K0H : S_K1H;
        const uint32_t qbH = par ? S_Q1H : S_Q0H;
        const uint32_t nqH = par ? S_Q0H : S_Q1H;
        float* Gs  = (float*)(sm + S_G)  + par * 64;
        float* WSs = (float*)(sm + S_WS) + par * 64;
        float* WGs = (float*)(sm + S_WG) + par * 64;
        float* EGs = (float*)(sm + S_EG) + par * 64;

        // ---- Q(c+1) prefetch (latency hides under GEMM1) ----
        const size_t tbq = tb0 + ((c + 1 < NCH) ? CC : 0);
        float4 qreg[4];
        #pragma unroll
        for (int ii = 0; ii < 4; ii++) {
            int i = tid + ii * NT;
            qreg[ii] = *(const float4*)(q + (tbq + (size_t)(i >> 5)) * 128 + ((i & 31) << 2));
        }

        // ---- GEMM1: S = Q K^T (ct<=rt) and QM0 = Q M^T (K=128), Q from smem ----
        float sS[2][4], sQ[2][4];
        #pragma unroll
        for (int j = 0; j < 2; j++)
            #pragma unroll
            for (int e = 0; e < 4; e++) { sS[j][e] = 0.f; sQ[j][e] = 0.f; }
        {
            const uint32_t qB = sb + qbH + (uint32_t)(rt * 16) * 272u + laneA272;
            const uint32_t col = (uint32_t)(ct * 16);
            #pragma unroll
            for (int ks = 0; ks < 8; ks++) {
                uint32_t qa[4], ql[4];
                ldmA(qa, qB + ks * 32);
                ldmA(ql, qB + 17408u + ks * 32);
                if (sact) {
                    uint32_t bh[4], bl[4];
                    uint32_t kB = sb + kbH + col * 272u + ks * 32 + laneB272x4;
                    ldmB4(bh, kB); ldmB4(bl, kB + 17408u);
                    mma16(sS[0], qa, bh[0], bh[1]); mma16(sS[0], qa, bl[0], bl[1]); mma16(sS[0], ql, bh[0], bh[1]);
                    mma16(sS[1], qa, bh[2], bh[3]); mma16(sS[1], qa, bl[2], bl[3]); mma16(sS[1], ql, bh[2], bh[3]);
                }
                {
                    uint32_t bh[4], bl[4];
                    uint32_t mB = sb + S_MH + col * 272u + ks * 32 + laneB272x4;
                    ldmB4(bh, mB); ldmB4(bl, mB + (S_ML - S_MH));
                    mma16(sQ[0], qa, bh[0], bh[1]); mma16(sQ[0], qa, bl[0], bl[1]); mma16(sQ[0], ql, bh[0], bh[1]);
                    mma16(sQ[1], qa, bh[2], bh[3]); mma16(sQ[1], qa, bl[2], bl[3]); mma16(sQ[1], ql, bh[2], bh[3]);
                }
            }
        }
        // ---- A build ----
        if (sact) {
            int t0 = rt * 16 + gid, t1 = t0 + 8;
            float g0 = Gs[t0], g1 = Gs[t1];
            #pragma unroll
            for (int j = 0; j < 2; j++) {
                int s0 = ct * 16 + 8 * j + 2 * tig, s1 = s0 + 1;
                float gs0 = Gs[s0], gs1 = Gs[s1], w0 = WSs[s0], w1 = WSs[s1];
                float a00 = (t0 >= s0) ? ex2n(g0 - gs0) * w0 * sS[j][0] : 0.f;
                float a01 = (t0 >= s1) ? ex2n(g0 - gs1) * w1 * sS[j][1] : 0.f;
                float a10 = (t1 >= s0) ? ex2n(g1 - gs0) * w0 * sS[j][2] : 0.f;
                float a11 = (t1 >= s1) ? ex2n(g1 - gs1) * w1 * sS[j][3] : 0.f;
                uint32_t hi, lo;
                sp2(a00, a01, hi, lo);
                uint32_t o = (uint32_t)t0 * 144u + (uint32_t)(s0 << 1);
                *(uint32_t*)(sm + S_AH + o) = hi; *(uint32_t*)(sm + S_AL + o) = lo;
                sp2(a10, a11, hi, lo);
                o = (uint32_t)t1 * 144u + (uint32_t)(s0 << 1);
                *(uint32_t*)(sm + S_AH + o) = hi; *(uint32_t*)(sm + S_AL + o) = lo;
            }
        }
        // ---- V^T(c) store ----
        #pragma unroll
        for (int ii = 0; ii < 8; ii++) {
            int i = tid + ii * NT;
            int s = i >> 6, n = i & 63;
            __nv_bfloat16 h, l; spl(vreg[ii], h, l);
            uint32_t o = (uint32_t)n * 144u + (uint32_t)(s << 1);
            *(__nv_bfloat16*)(sm + S_VH + o) = h;
            *(__nv_bfloat16*)(sm + S_VL + o) = l;
        }
        // ---- Q(c+1) STS (other buffer; consumers read after sync B) ----
        #pragma unroll
        for (int ii = 0; ii < 4; ii++) {
            int i = tid + ii * NT;
            int t = i >> 5, c4 = (i & 31) << 2;
            uint32_t o = (uint32_t)t * 272u + (uint32_t)(c4 << 1);
            uint32_t h0, l0, h1, l1;
            sp2(qreg[ii].x, qreg[ii].y, h0, l0); sp2(qreg[ii].z, qreg[ii].w, h1, l1);
            *(uint32_t*)(sm + nqH + o) = h0; *(uint32_t*)(sm + nqH + o + 4) = h1;
            *(uint32_t*)(sm + nqH + 17408u + o) = l0; *(uint32_t*)(sm + nqH + 17408u + o + 4) = l1;
        }
        __syncthreads();   // sync A: A(c) + V^T(c) visible

        // ---- scalars(c+1) (warp 0, overlapped) ----
        if (warp == 0 && c + 1 < NCH) do_scalars(tb0 + CC, par ^ 1);

        // ---- K(c+1) + V(c+1) prefetch ----
        const size_t tb1 = tb0 + ((c + 1 < NCH) ? CC : 0);
        float4 kreg[4];
        #pragma unroll
        for (int ii = 0; ii < 4; ii++) {
            int i = tid + ii * NT;
            kreg[ii] = *(const float4*)(kk + (tb1 + (size_t)(i >> 5)) * 128 + ((i & 31) << 2));
        }
        #pragma unroll
        for (int ii = 0; ii < 8; ii++) {
            int i = tid + ii * NT;
            vreg[ii] = v[(tb1 + (size_t)(i >> 6)) * 128 + vh * 64 + (i & 63)];
        }

        // ---- GEMM2: AV (ks<=rt); dM into pre-scaled m0 ----
        float sA[2][4];
        #pragma unroll
        for (int j = 0; j < 2; j++)
            #pragma unroll
            for (int e = 0; e < 4; e++) sA[j][e] = 0.f;
        {
            const uint32_t ahB = sb + S_AH + (uint32_t)(rt * 16) * 144u + laneA144;
            #pragma unroll
            for (int ks = 0; ks < 4; ks++) {
                if (ks <= rt) {
                    uint32_t aa[4], al[4];
                    ldmA(aa, ahB + ks * 32); ldmA(al, ahB + (S_AL - S_AH) + ks * 32);
                    uint32_t bh[4], bl[4];
                    uint32_t vB = sb + S_VH + (uint32_t)(ct * 16) * 144u + ks * 32 + laneB144x4;
                    ldmB4(bh, vB); ldmB4(bl, vB + (S_VL - S_VH));
                    mma16(sA[0], aa, bh[0], bh[1]); mma16(sA[0], aa, bl[0], bl[1]); mma16(sA[0], al, bh[0], bh[1]);
                    mma16(sA[1], aa, bh[2], bh[3]); mma16(sA[1], aa, bl[2], bl[3]); mma16(sA[1], al, bh[2], bh[3]);
                }
            }
            float s63 = ((float*)(sm + S_SC))[par];
            #pragma unroll
            for (int j = 0; j < 4; j++)
                #pragma unroll
                for (int e = 0; e < 4; e++) m0[j][e] *= s63;
            const uint32_t ktB = sb + kbH + laneT + ((uint32_t)(wr * 16) << 1);
            #pragma unroll
            for (int ks = 0; ks < 4; ks++) {
                uint32_t kh4[4], kl4[4];
                ldmT(kh4, ktB + (uint32_t)(ks * 16) * 272u);
                ldmT(kl4, ktB + 17408u + (uint32_t)(ks * 16) * 272u);
                int sA0 = ks * 16 + 2 * tig;
                float wg0 = WGs[sA0], wg1 = WGs[sA0 + 1];
                float wg2 = WGs[sA0 + 8], wg3 = WGs[sA0 + 9];
                uint32_t ka[4], kb2[4];
                #pragma unroll
                for (int p = 0; p < 4; p++) {
                    float sw0 = (p < 2) ? wg0 : wg2;
                    float sw1 = (p < 2) ? wg1 : wg3;
                    __nv_bfloat162 H = *(__nv_bfloat162*)&kh4[p];
                    __nv_bfloat162 L = *(__nv_bfloat162*)&kl4[p];
                    float v0 = (__bfloat162float(H.x) + __bfloat162float(L.x)) * sw0;
                    float v1 = (__bfloat162float(H.y) + __bfloat162float(L.y)) * sw1;
                    sp2(v0, v1, ka[p], kb2[p]);
                }
                #pragma unroll
                for (int jj = 0; jj < 2; jj++) {
                    uint32_t bh[4], bl[4];
                    uint32_t vB = sb + S_VH + (uint32_t)(wc * 32 + 16 * jj) * 144u + ks * 32 + laneB144x4;
                    ldmB4(bh, vB); ldmB4(bl, vB + (S_VL - S_VH));
                    mma16(m0[2*jj],   ka, bh[0], bh[1]); mma16(m0[2*jj],   ka, bl[0], bl[1]); mma16(m0[2*jj],   kb2, bh[0], bh[1]);
                    mma16(m0[2*jj+1], ka, bh[2], bh[3]); mma16(m0[2*jj+1], ka, bl[2], bl[3]); mma16(m0[2*jj+1], kb2, bh[2], bh[3]);
                }
            }
        }
        // ---- readout ----
        {
            int t0 = rt * 16 + gid, t1 = t0 + 8;
            float e0 = EGs[t0], e1 = EGs[t1];
            #pragma unroll
            for (int j = 0; j < 2; j++) {
                int n = ct * 16 + 8 * j + 2 * tig;
                float2 o0 = make_float2(fmaf(e0, sQ[j][0], sA[j][0]), fmaf(e0, sQ[j][1], sA[j][1]));
                float2 o1 = make_float2(fmaf(e1, sQ[j][2], sA[j][2]), fmaf(e1, sQ[j][3], sA[j][3]));
                *(float2*)(out + (tb0 + t0) * 128 + vh * 64 + n) = o0;
                *(float2*)(out + (tb0 + t1) * 128 + vh * 64 + n) = o1;
            }
        }
        // ---- K(c+1) STS ----
        #pragma unroll
        for (int ii = 0; ii < 4; ii++) {
            int i = tid + ii * NT;
            int t = i >> 5, c4 = (i & 31) << 2;
            uint32_t o = (uint32_t)t * 272u + (uint32_t)(c4 << 1);
            uint32_t h0, l0, h1, l1;
            sp2(kreg[ii].x, kreg[ii].y, h0, l0); sp2(kreg[ii].z, kreg[ii].w, h1, l1);
            *(uint32_t*)(sm + nbH + o) = h0; *(uint32_t*)(sm + nbH + o + 4) = h1;
            *(uint32_t*)(sm + nbH + 17408u + o) = l0; *(uint32_t*)(sm + nbH + 17408u + o + 4) = l1;
        }
        // ---- M^T(c+1) from updated m0 regs ----
        #pragma unroll
        for (int j = 0; j < 4; j++) {
            int n = wc * 32 + 8 * j + 2 * tig;
            #pragma unroll
            for (int e = 0; e < 4; e++) {
                int nn = n + (e & 1), m = (e < 2) ? mr0 : mr1;
                __nv_bfloat16 h, l; spl(m0[j][e], h, l);
                uint32_t o = (uint32_t)nn * 272u + ((uint32_t)m << 1);
                *(__nv_bfloat16*)(sm + S_MH + o) = h;
                *(__nv_bfloat16*)(sm + S_ML + o) = l;
            }
        }
        __syncthreads();   // sync B: K(c+1), Q(c+1), M^T(c+1), scalars(c+1) visible
    }
}

extern "C" void kernel_launch(void* const* d_in, const int* in_sizes, int n_in,
                              void* d_out, int out_size)
{
    (void)in_sizes; (void)n_in; (void)out_size;
    cudaFuncSetAttribute(lmm_hmma, cudaFuncAttributeMaxDynamicSharedMemorySize, SMEMB);
    lmm_hmma<<<128, NT, SMEMB>>>((const float*)d_in[0], (const float*)d_in[1],
                                 (const float*)d_in[2], (const float*)d_in[3],
                                 (const float*)d_in[4], (const float*)d_in[5],
                                 (const float*)d_in[6], (float*)d_out);
}

// round 17
// speedup vs baseline: 1.6254x; 1.0213x over previous
#include <cuda_runtime.h>
#include <cuda_bf16.h>
#include <cstdint>

#define TT 2048
#define CC 64
#define NCH 32
#define NT 512

// K tiles [64s x 128m] stride 272, double-buffered. Q tiles same, double-buffered.
// MT [64n x 128m] 272. VT [64n x 64s] 144. A [64t x 64s] 144. Scalars parity 2x64.
#define S_K0H 0
#define S_K0L 17408
#define S_K1H 34816
#define S_K1L 52224
#define S_MH  69632
#define S_ML  87040
#define S_VH  104448
#define S_VL  113664
#define S_AH  122880
#define S_AL  132096
#define S_G   141312
#define S_WS  141824
#define S_WG  142336
#define S_EG  142848
#define S_SC  143360
#define S_Q0H 143392
#define S_Q0L 160800
#define S_Q1H 178208
#define S_Q1L 195616
#define SMEMB 213024

// warp -> (rt, ct) permutation balancing S-triangle + AV cost across SMSPs (warp%4)
#define RT_TBL 0x40166FAFu
#define CT_TBL 0xF90B5D88u

static __device__ __forceinline__ uint32_t su32(const void* p) {
    uint32_t a;
    asm("{ .reg .u64 t; cvta.to.shared.u64 t, %1; cvt.u32.u64 %0, t; }" : "=r"(a) : "l"(p));
    return a;
}
static __device__ __forceinline__ void ldmA(uint32_t a[4], uint32_t addr) {
    asm volatile("ldmatrix.sync.aligned.m8n8.x4.shared.b16 {%0,%1,%2,%3}, [%4];"
        : "=r"(a[0]), "=r"(a[1]), "=r"(a[2]), "=r"(a[3]) : "r"(addr));
}
static __device__ __forceinline__ void ldmB4(uint32_t b[4], uint32_t addr) {
    asm volatile("ldmatrix.sync.aligned.m8n8.x4.shared.b16 {%0,%1,%2,%3}, [%4];"
        : "=r"(b[0]), "=r"(b[1]), "=r"(b[2]), "=r"(b[3]) : "r"(addr));
}
static __device__ __forceinline__ void ldmT(uint32_t a[4], uint32_t addr) {
    asm volatile("ldmatrix.sync.aligned.m8n8.x4.trans.shared.b16 {%0,%1,%2,%3}, [%4];"
        : "=r"(a[0]), "=r"(a[1]), "=r"(a[2]), "=r"(a[3]) : "r"(addr));
}
static __device__ __forceinline__ void mma16(float c[4], const uint32_t a[4], uint32_t b0, uint32_t b1) {
    asm volatile("mma.sync.aligned.m16n8k16.row.col.f32.bf16.bf16.f32 "
        "{%0,%1,%2,%3}, {%4,%5,%6,%7}, {%8,%9}, {%0,%1,%2,%3};"
        : "+f"(c[0]), "+f"(c[1]), "+f"(c[2]), "+f"(c[3])
        : "r"(a[0]), "r"(a[1]), "r"(a[2]), "r"(a[3]), "r"(b0), "r"(b1));
}
static __device__ __forceinline__ void spl(float x, __nv_bfloat16& h, __nv_bfloat16& l) {
    h = __float2bfloat16_rn(x);
    l = __float2bfloat16_rn(x - __bfloat162float(h));
}
static __device__ __forceinline__ void sp2(float x0, float x1, uint32_t& hi, uint32_t& lo) {
    __nv_bfloat16 h0, l0, h1, l1;
    spl(x0, h0, l0); spl(x1, h1, l1);
    hi = (uint32_t)__bfloat16_as_ushort(h0) | ((uint32_t)__bfloat16_as_ushort(h1) << 16);
    lo = (uint32_t)__bfloat16_as_ushort(l0) | ((uint32_t)__bfloat16_as_ushort(l1) << 16);
}
// exp2(x) for x <= 0, FFMA-only
static __device__ __forceinline__ float ex2n(float x) {
    float xc = fmaxf(x, -150.f);
    float xf = floorf(xc);
    float f  = xc - xf;
    float p = 1.54035e-4f;
    p = fmaf(p, f, 1.3335581e-3f);
    p = fmaf(p, f, 9.6181291e-3f);
    p = fmaf(p, f, 5.5504109e-2f);
    p = fmaf(p, f, 2.4022651e-1f);
    p = fmaf(p, f, 6.9314718e-1f);
    p = fmaf(p, f, 1.0f);
    float r = __int_as_float(__float_as_int(p) + (((int)xf) << 23));
    return (xc <= -126.f) ? 0.f : r;
}

__global__ void __launch_bounds__(NT, 1)
lmm_hmma(const float* __restrict__ q, const float* __restrict__ kk,
         const float* __restrict__ v, const float* __restrict__ alpha,
         const float* __restrict__ rho, const float* __restrict__ lam,
         const float* __restrict__ init, float* __restrict__ out)
{
    extern __shared__ char sm[];
    const uint32_t sb = su32(sm);
    const int tid = threadIdx.x, warp = tid >> 5, lane = tid & 31;
    const int gid = lane >> 2, tig = lane & 3;
    const int b = blockIdx.x >> 1, vh = blockIdx.x & 1;
    const int rt = (int)((RT_TBL >> (2 * warp)) & 3u);
    const int ct = (int)((CT_TBL >> (2 * warp)) & 3u);
    const int wr = warp >> 1, wc = warp & 1;
    const bool sact = (ct <= rt);

    const uint32_t laneA272 = (uint32_t)(lane & 15) * 272u + (uint32_t)((lane >> 4) << 4);
    const uint32_t laneA144 = (uint32_t)(lane & 15) * 144u + (uint32_t)((lane >> 4) << 4);
    const uint32_t laneB272x4 = (uint32_t)(lane & 7) * 272u + (uint32_t)(((lane >> 3) & 1) << 4)
                              + (uint32_t)(lane >> 4) * (8u * 272u);
    const uint32_t laneB144x4 = (uint32_t)(lane & 7) * 144u + (uint32_t)(((lane >> 3) & 1) << 4)
                              + (uint32_t)(lane >> 4) * (8u * 144u);
    const uint32_t laneT = ((uint32_t)(lane & 7) + (uint32_t)((lane >> 4) << 3)) * 272u
                         + (uint32_t)(lane & 8) * 2u;

    auto do_scalars = [&](size_t tbX, int parX) {
        float* Gp  = (float*)(sm + S_G)  + parX * 64;
        float* WSp = (float*)(sm + S_WS) + parX * 64;
        float* WGp = (float*)(sm + S_WG) + parX * 64;
        float* EGp = (float*)(sm + S_EG) + parX * 64;
        float x = log2f(fmaxf(lam[tbX + lane], 1e-37f));
        #pragma unroll
        for (int o = 1; o < 32; o <<= 1) { float y = __shfl_up_sync(~0u, x, o); if (lane >= o) x += y; }
        float tot = __shfl_sync(~0u, x, 31);
        float y2 = log2f(fmaxf(lam[tbX + 32 + lane], 1e-37f));
        #pragma unroll
        for (int o = 1; o < 32; o <<= 1) { float y = __shfl_up_sync(~0u, y2, o); if (lane >= o) y2 += y; }
        float g2 = tot + y2;
        float g63 = __shfl_sync(~0u, g2, 31);
        float w0 = rho[tbX + lane] * alpha[tbX + lane];
        float w1 = rho[tbX + 32 + lane] * alpha[tbX + 32 + lane];
        Gp[lane] = x;            Gp[32 + lane] = g2;
        WSp[lane] = w0;          WSp[32 + lane] = w1;
        EGp[lane] = ex2n(x);     EGp[32 + lane] = ex2n(g2);
        WGp[lane] = ex2n(g63 - x) * w0;
        WGp[32 + lane] = ex2n(g63 - g2) * w1;
        if (lane == 31) ((float*)(sm + S_SC))[parX] = ex2n(g63);
    };

    // ---- M0 in registers ----
    const int mr0 = wr * 16 + gid, mr1 = mr0 + 8;
    float m0[4][4];
    {
        const float* ip = init + (size_t)b * 16384 + vh * 64;
        #pragma unroll
        for (int j = 0; j < 4; j++) {
            int n = wc * 32 + 8 * j + 2 * tig;
            float2 f0 = *(const float2*)(ip + (size_t)mr0 * 128 + n);
            float2 f1 = *(const float2*)(ip + (size_t)mr1 * 128 + n);
            m0[j][0] = f0.x; m0[j][1] = f0.y; m0[j][2] = f1.x; m0[j][3] = f1.y;
        }
    }
    #pragma unroll
    for (int j = 0; j < 4; j++) {
        int n = wc * 32 + 8 * j + 2 * tig;
        #pragma unroll
        for (int e = 0; e < 4; e++) {
            int nn = n + (e & 1), m = (e < 2) ? mr0 : mr1;
            __nv_bfloat16 h, l; spl(m0[j][e], h, l);
            uint32_t o = (uint32_t)nn * 272u + ((uint32_t)m << 1);
            *(__nv_bfloat16*)(sm + S_MH + o) = h;
            *(__nv_bfloat16*)(sm + S_ML + o) = l;
        }
    }
    // K(0) and Q(0) tiles -> buf0
    {
        const size_t t0 = (size_t)b * TT;
        for (int i = tid; i < 2048; i += NT) {
            int t = i >> 5, c4 = (i & 31) << 2;
            uint32_t o = (uint32_t)t * 272u + (uint32_t)(c4 << 1);
            float4 f = *(const float4*)(kk + (t0 + t) * 128 + c4);
            uint32_t h0, l0, h1, l1;
            sp2(f.x, f.y, h0, l0); sp2(f.z, f.w, h1, l1);
            *(uint32_t*)(sm + S_K0H + o) = h0; *(uint32_t*)(sm + S_K0H + o + 4) = h1;
            *(uint32_t*)(sm + S_K0L + o) = l0; *(uint32_t*)(sm + S_K0L + o + 4) = l1;
            f = *(const float4*)(q + (t0 + t) * 128 + c4);
            sp2(f.x, f.y, h0, l0); sp2(f.z, f.w, h1, l1);
            *(uint32_t*)(sm + S_Q0H + o) = h0; *(uint32_t*)(sm + S_Q0H + o + 4) = h1;
            *(uint32_t*)(sm + S_Q0L + o) = l0; *(uint32_t*)(sm + S_Q0L + o + 4) = l1;
        }
    }
    if (warp == 0) do_scalars((size_t)b * TT, 0);
    float vreg[8];
    #pragma unroll
    for (int ii = 0; ii < 8; ii++) {
        int i = tid + ii * NT;
        vreg[ii] = v[((size_t)b * TT + (size_t)(i >> 6)) * 128 + vh * 64 + (i & 63)];
    }
    __syncthreads();   // prologue: K(0), Q(0), M^T(0), scalars(0) visible

    for (int c = 0; c < NCH; c++) {
        const size_t tb0 = (size_t)b * TT + (size_t)c * CC;
        const int par = c & 1;
        const uint32_t kbH = par ? S_K1H : S_K0H;
        const uint32_t nbH = par ? S_K0H : S_K1H;
        const uint32_t qbH = par ? S_Q1H : S_Q0H;
        const uint32_t nqH = par ? S_Q0H : S_Q1H;
        float* Gs  = (float*)(sm + S_G)  + par * 64;
        float* WSs = (float*)(sm + S_WS) + par * 64;
        float* WGs = (float*)(sm + S_WG) + par * 64;
        float* EGs = (float*)(sm + S_EG) + par * 64;

        // ---- Q(c+1) prefetch (latency hides under GEMM1) ----
        const size_t tbq = tb0 + ((c + 1 < NCH) ? CC : 0);
        float4 qreg[4];
        #pragma unroll
        for (int ii = 0; ii < 4; ii++) {
            int i = tid + ii * NT;
            qreg[ii] = *(const float4*)(q + (tbq + (size_t)(i >> 5)) * 128 + ((i & 31) << 2));
        }

        // ---- GEMM1: S = Q K^T (sact) and QM0 = Q M^T (K=128), Q from smem ----
        float sS[2][4], sQ[2][4];
        #pragma unroll
        for (int j = 0; j < 2; j++)
            #pragma unroll
            for (int e = 0; e < 4; e++) { sS[j][e] = 0.f; sQ[j][e] = 0.f; }
        {
            const uint32_t qB = sb + qbH + (uint32_t)(rt * 16) * 272u + laneA272;
            const uint32_t col = (uint32_t)(ct * 16);
            #pragma unroll
            for (int ks = 0; ks < 8; ks++) {
                uint32_t qa[4], ql[4];
                ldmA(qa, qB + ks * 32);
                ldmA(ql, qB + 17408u + ks * 32);
                if (sact) {
                    uint32_t bh[4], bl[4];
                    uint32_t kB = sb + kbH + col * 272u + ks * 32 + laneB272x4;
                    ldmB4(bh, kB); ldmB4(bl, kB + 17408u);
                    mma16(sS[0], qa, bh[0], bh[1]); mma16(sS[0], qa, bl[0], bl[1]); mma16(sS[0], ql, bh[0], bh[1]);
                    mma16(sS[1], qa, bh[2], bh[3]); mma16(sS[1], qa, bl[2], bl[3]); mma16(sS[1], ql, bh[2], bh[3]);
                }
                {
                    uint32_t bh[4], bl[4];
                    uint32_t mB = sb + S_MH + col * 272u + ks * 32 + laneB272x4;
                    ldmB4(bh, mB); ldmB4(bl, mB + (S_ML - S_MH));
                    mma16(sQ[0], qa, bh[0], bh[1]); mma16(sQ[0], qa, bl[0], bl[1]); mma16(sQ[0], ql, bh[0], bh[1]);
                    mma16(sQ[1], qa, bh[2], bh[3]); mma16(sQ[1], qa, bl[2], bl[3]); mma16(sQ[1], ql, bh[2], bh[3]);
                }
            }
        }
        // ---- A build ----
        if (sact) {
            int t0 = rt * 16 + gid, t1 = t0 + 8;
            float g0 = Gs[t0], g1 = Gs[t1];
            #pragma unroll
            for (int j = 0; j < 2; j++) {
                int s0 = ct * 16 + 8 * j + 2 * tig, s1 = s0 + 1;
                float gs0 = Gs[s0], gs1 = Gs[s1], w0 = WSs[s0], w1 = WSs[s1];
                float a00 = (t0 >= s0) ? ex2n(g0 - gs0) * w0 * sS[j][0] : 0.f;
                float a01 = (t0 >= s1) ? ex2n(g0 - gs1) * w1 * sS[j][1] : 0.f;
                float a10 = (t1 >= s0) ? ex2n(g1 - gs0) * w0 * sS[j][2] : 0.f;
                float a11 = (t1 >= s1) ? ex2n(g1 - gs1) * w1 * sS[j][3] : 0.f;
                uint32_t hi, lo;
                sp2(a00, a01, hi, lo);
                uint32_t o = (uint32_t)t0 * 144u + (uint32_t)(s0 << 1);
                *(uint32_t*)(sm + S_AH + o) = hi; *(uint32_t*)(sm + S_AL + o) = lo;
                sp2(a10, a11, hi, lo);
                o = (uint32_t)t1 * 144u + (uint32_t)(s0 << 1);
                *(uint32_t*)(sm + S_AH + o) = hi; *(uint32_t*)(sm + S_AL + o) = lo;
            }
        }
        // ---- V^T(c) store ----
        #pragma unroll
        for (int ii = 0; ii < 8; ii++) {
            int i = tid + ii * NT;
            int s = i >> 6, n = i & 63;
            __nv_bfloat16 h, l; spl(vreg[ii], h, l);
            uint32_t o = (uint32_t)n * 144u + (uint32_t)(s << 1);
            *(__nv_bfloat16*)(sm + S_VH + o) = h;
            *(__nv_bfloat16*)(sm + S_VL + o) = l;
        }
        // ---- Q(c+1) STS (other buffer; consumers read after sync B) ----
        #pragma unroll
        for (int ii = 0; ii < 4; ii++) {
            int i = tid + ii * NT;
            int t = i >> 5, c4 = (i & 31) << 2;
            uint32_t o = (uint32_t)t * 272u + (uint32_t)(c4 << 1);
            uint32_t h0, l0, h1, l1;
            sp2(qreg[ii].x, qreg[ii].y, h0, l0); sp2(qreg[ii].z, qreg[ii].w, h1, l1);
            *(uint32_t*)(sm + nqH + o) = h0; *(uint32_t*)(sm + nqH + o + 4) = h1;
            *(uint32_t*)(sm + nqH + 17408u + o) = l0; *(uint32_t*)(sm + nqH + 17408u + o + 4) = l1;
        }
        __syncthreads();   // sync A: A(c) + V^T(c) visible

        // ---- scalars(c+1) (warp 0, overlapped) ----
        if (warp == 0 && c + 1 < NCH) do_scalars(tb0 + CC, par ^ 1);

        // ---- K(c+1) + V(c+1) prefetch ----
        const size_t tb1 = tb0 + ((c + 1 < NCH) ? CC : 0);
        float4 kreg[4];
        #pragma unroll
        for (int ii = 0; ii < 4; ii++) {
            int i = tid + ii * NT;
            kreg[ii] = *(const float4*)(kk + (tb1 + (size_t)(i >> 5)) * 128 + ((i & 31) << 2));
        }
        #pragma unroll
        for (int ii = 0; ii < 8; ii++) {
            int i = tid + ii * NT;
            vreg[ii] = v[(tb1 + (size_t)(i >> 6)) * 128 + vh * 64 + (i & 63)];
        }

        // ---- GEMM2: AV (ks<=rt); dM into pre-scaled m0 ----
        float sA[2][4];
        #pragma unroll
        for (int j = 0; j < 2; j++)
            #pragma unroll
            for (int e = 0; e < 4; e++) sA[j][e] = 0.f;
        {
            const uint32_t ahB = sb + S_AH + (uint32_t)(rt * 16) * 144u + laneA144;
            #pragma unroll
            for (int ks = 0; ks < 4; ks++) {
                if (ks <= rt) {
                    uint32_t aa[4], al[4];
                    ldmA(aa, ahB + ks * 32); ldmA(al, ahB + (S_AL - S_AH) + ks * 32);
                    uint32_t bh[4], bl[4];
                    uint32_t vB = sb + S_VH + (uint32_t)(ct * 16) * 144u + ks * 32 + laneB144x4;
                    ldmB4(bh, vB); ldmB4(bl, vB + (S_VL - S_VH));
                    mma16(sA[0], aa, bh[0], bh[1]); mma16(sA[0], aa, bl[0], bl[1]); mma16(sA[0], al, bh[0], bh[1]);
                    mma16(sA[1], aa, bh[2], bh[3]); mma16(sA[1], aa, bl[2], bl[3]); mma16(sA[1], al, bh[2], bh[3]);
                }
            }
            float s63 = ((float*)(sm + S_SC))[par];
            #pragma unroll
            for (int j = 0; j < 4; j++)
                #pragma unroll
                for (int e = 0; e < 4; e++) m0[j][e] *= s63;
            const uint32_t ktB = sb + kbH + laneT + ((uint32_t)(wr * 16) << 1);
            #pragma unroll
            for (int ks = 0; ks < 4; ks++) {
                uint32_t kh4[4], kl4[4];
                ldmT(kh4, ktB + (uint32_t)(ks * 16) * 272u);
                ldmT(kl4, ktB + 17408u + (uint32_t)(ks * 16) * 272u);
                int sA0 = ks * 16 + 2 * tig;
                float wg0 = WGs[sA0], wg1 = WGs[sA0 + 1];
                float wg2 = WGs[sA0 + 8], wg3 = WGs[sA0 + 9];
                uint32_t ka[4], kb2[4];
                #pragma unroll
                for (int p = 0; p < 4; p++) {
                    float sw0 = (p < 2) ? wg0 : wg2;
                    float sw1 = (p < 2) ? wg1 : wg3;
                    __nv_bfloat162 H = *(__nv_bfloat162*)&kh4[p];
                    __nv_bfloat162 L = *(__nv_bfloat162*)&kl4[p];
                    float v0 = (__bfloat162float(H.x) + __bfloat162float(L.x)) * sw0;
                    float v1 = (__bfloat162float(H.y) + __bfloat162float(L.y)) * sw1;
                    sp2(v0, v1, ka[p], kb2[p]);
                }
                #pragma unroll
                for (int jj = 0; jj < 2; jj++) {
                    uint32_t bh[4], bl[4];
                    uint32_t vB = sb + S_VH + (uint32_t)(wc * 32 + 16 * jj) * 144u + ks * 32 + laneB144x4;
                    ldmB4(bh, vB); ldmB4(bl, vB + (S_VL - S_VH));
                    mma16(m0[2*jj],   ka, bh[0], bh[1]); mma16(m0[2*jj],   ka, bl[0], bl[1]); mma16(m0[2*jj],   kb2, bh[0], bh[1]);
                    mma16(m0[2*jj+1], ka, bh[2], bh[3]); mma16(m0[2*jj+1], ka, bl[2], bl[3]); mma16(m0[2*jj+1], kb2, bh[2], bh[3]);
                }
            }
        }
        // ---- readout ----
        {
            int t0 = rt * 16 + gid, t1 = t0 + 8;
            float e0 = EGs[t0], e1 = EGs[t1];
            #pragma unroll
            for (int j = 0; j < 2; j++) {
                int n = ct * 16 + 8 * j + 2 * tig;
                float2 o0 = make_float2(fmaf(e0, sQ[j][0], sA[j][0]), fmaf(e0, sQ[j][1], sA[j][1]));
                float2 o1 = make_float2(fmaf(e1, sQ[j][2], sA[j][2]), fmaf(e1, sQ[j][3], sA[j][3]));
                *(float2*)(out + (tb0 + t0) * 128 + vh * 64 + n) = o0;
                *(float2*)(out + (tb0 + t1) * 128 + vh * 64 + n) = o1;
            }
        }
        // ---- K(c+1) STS ----
        #pragma unroll
        for (int ii = 0; ii < 4; ii++) {
            int i = tid + ii * NT;
            int t = i >> 5, c4 = (i & 31) << 2;
            uint32_t o = (uint32_t)t * 272u + (uint32_t)(c4 << 1);
            uint32_t h0, l0, h1, l1;
            sp2(kreg[ii].x, kreg[ii].y, h0, l0); sp2(kreg[ii].z, kreg[ii].w, h1, l1);
            *(uint32_t*)(sm + nbH + o) = h0; *(uint32_t*)(sm + nbH + o + 4) = h1;
            *(uint32_t*)(sm + nbH + 17408u + o) = l0; *(uint32_t*)(sm + nbH + 17408u + o + 4) = l1;
        }
        // ---- M^T(c+1) from updated m0 regs ----
        #pragma unroll
        for (int j = 0; j < 4; j++) {
            int n = wc * 32 + 8 * j + 2 * tig;
            #pragma unroll
            for (int e = 0; e < 4; e++) {
                int nn = n + (e & 1), m = (e < 2) ? mr0 : mr1;
                __nv_bfloat16 h, l; spl(m0[j][e], h, l);
                uint32_t o = (uint32_t)nn * 272u + ((uint32_t)m << 1);
                *(__nv_bfloat16*)(sm + S_MH + o) = h;
                *(__nv_bfloat16*)(sm + S_ML + o) = l;
            }
        }
        __syncthreads();   // sync B: K(c+1), Q(c+1), M^T(c+1), scalars(c+1) visible
    }
}

extern "C" void kernel_launch(void* const* d_in, const int* in_sizes, int n_in,
                              void* d_out, int out_size)
{
    (void)in_sizes; (void)n_in; (void)out_size;
    cudaFuncSetAttribute(lmm_hmma, cudaFuncAttributeMaxDynamicSharedMemorySize, SMEMB);
    lmm_hmma<<<128, NT, SMEMB>>>((const float*)d_in[0], (const float*)d_in[1],
                                 (const float*)d_in[2], (const float*)d_in[3],
                                 (const float*)d_in[4], (const float*)d_in[5],
                                 (const float*)d_in[6], (float*)d_out);
}